// round 2
// baseline (speedup 1.0000x reference)
#include <cuda_runtime.h>
#include <math.h>

#define B_  16384
#define S_  256
#define E_  128
#define H_  128
#define N_  34

// output layout (floats): rep_vec [B,384] | log_task_prob [B,34] | latent_target [B,128] | latent_vec [B,128]
#define REP_OFF  0
#define LP_OFF   (B_*(S_+E_))                // 6291456
#define LT_OFF   (LP_OFF + B_*N_)            // 6848512
#define LV_OFF   (LT_OFF + B_*E_)            // 8945664

__device__ float g_cos[(size_t)B_*N_];   // cos_sim scratch
__device__ float g_lat[(size_t)B_*E_];   // latent_vec accumulator

// smem layout (floats)
#define ACT_STRIDE 130
#define ACT_FLOATS (128*ACT_STRIDE)   // 16640
#define AS_FLOATS  (128*33)           // 4224
#define BS_FLOATS  (32*128)           // 4096
#define SMEM_FLOATS (ACT_FLOATS + AS_FLOATS + BS_FLOATS + 3*128)
#define SMEM_BYTES  (SMEM_FLOATS * sizeof(float))

__global__ void zero_lat_kernel() {
    int idx = blockIdx.x * blockDim.x + threadIdx.x;   // grid 2048 x 256 -> 524288 = B_*E_/4
    float4 z = make_float4(0.f, 0.f, 0.f, 0.f);
    reinterpret_cast<float4*>(g_lat)[idx] = z;
}

// GEMM stage with A = Act (smem, [128][ACT_STRIDE]) and B = Wn ([K,128] row-major in gmem)
__device__ __forceinline__ void gemm_stage(float acc[8][8], const float* __restrict__ Wn,
                                           const float* Act, float* Bs,
                                           int tid, int tx, int ty, int K)
{
    for (int k0 = 0; k0 < K; k0 += 32) {
        __syncthreads();
        #pragma unroll
        for (int idx = tid; idx < 1024; idx += 256) {
            int k = idx >> 5, c = (idx & 31) << 2;
            *(float4*)(Bs + k*128 + c) = *(const float4*)(Wn + (size_t)(k0+k)*128 + c);
        }
        __syncthreads();
        #pragma unroll
        for (int k = 0; k < 32; k++) {
            float a[8];
            #pragma unroll
            for (int i = 0; i < 8; i++) a[i] = Act[(ty*8+i)*ACT_STRIDE + k0 + k];
            float4 u = *(const float4*)(Bs + k*128 + tx*8);
            float4 v = *(const float4*)(Bs + k*128 + tx*8 + 4);
            float bb[8] = {u.x,u.y,u.z,u.w,v.x,v.y,v.z,v.w};
            #pragma unroll
            for (int i = 0; i < 8; i++)
                #pragma unroll
                for (int j = 0; j < 8; j++) acc[i][j] = fmaf(a[i], bb[j], acc[i][j]);
        }
    }
}

__global__ __launch_bounds__(256, 2) void enc_main(
    const float* __restrict__ state, const int* __restrict__ task_id,
    const float* __restrict__ prior,
    const float* __restrict__ W1, const float* __restrict__ b1,
    const float* __restrict__ W2, const float* __restrict__ b2,
    const float* __restrict__ W3, const float* __restrict__ b3,
    const float* __restrict__ lang, float* __restrict__ out_lt)
{
    extern __shared__ float sm[];
    float* Act  = sm;
    float* As   = sm + ACT_FLOATS;
    float* Bs   = As + AS_FLOATS;
    float* pw   = Bs + BS_FLOATS;   // p(prior)_n * inv_norm_q per row
    float* invq = pw + 128;
    int*   trow = (int*)(invq + 128);

    const int n   = blockIdx.x;
    const int b0  = blockIdx.y * 128;
    const int tid = threadIdx.x;
    const int tx  = tid & 15, ty = tid >> 4;

    float acc[8][8];
    #pragma unroll
    for (int i = 0; i < 8; i++)
        #pragma unroll
        for (int j = 0; j < 8; j++) acc[i][j] = 0.f;

    // ---------- stage 1: state[128,256] @ W1[n] -> relu -> Act ----------
    const float* W1n = W1 + (size_t)n * S_ * H_;
    for (int k0 = 0; k0 < S_; k0 += 32) {
        __syncthreads();
        #pragma unroll
        for (int idx = tid; idx < 1024; idx += 256) {
            int row = idx >> 3, p = (idx & 7) << 2;
            float4 v = *(const float4*)(state + (size_t)(b0+row)*S_ + k0 + p);
            float* d = As + row*33 + p;
            d[0]=v.x; d[1]=v.y; d[2]=v.z; d[3]=v.w;
        }
        #pragma unroll
        for (int idx = tid; idx < 1024; idx += 256) {
            int k = idx >> 5, c = (idx & 31) << 2;
            *(float4*)(Bs + k*128 + c) = *(const float4*)(W1n + (size_t)(k0+k)*128 + c);
        }
        __syncthreads();
        #pragma unroll
        for (int k = 0; k < 32; k++) {
            float a[8];
            #pragma unroll
            for (int i = 0; i < 8; i++) a[i] = As[(ty*8+i)*33 + k];
            float4 u = *(const float4*)(Bs + k*128 + tx*8);
            float4 v = *(const float4*)(Bs + k*128 + tx*8 + 4);
            float bb[8] = {u.x,u.y,u.z,u.w,v.x,v.y,v.z,v.w};
            #pragma unroll
            for (int i = 0; i < 8; i++)
                #pragma unroll
                for (int j = 0; j < 8; j++) acc[i][j] = fmaf(a[i], bb[j], acc[i][j]);
        }
    }
    {
        const float* bp = b1 + n*H_;
        float4 u = *(const float4*)(bp + tx*8);
        float4 v = *(const float4*)(bp + tx*8 + 4);
        float bb[8] = {u.x,u.y,u.z,u.w,v.x,v.y,v.z,v.w};
        __syncthreads();
        #pragma unroll
        for (int i = 0; i < 8; i++)
            #pragma unroll
            for (int j = 0; j < 8; j++) {
                Act[(ty*8+i)*ACT_STRIDE + tx*8 + j] = fmaxf(acc[i][j] + bb[j], 0.f);
                acc[i][j] = 0.f;
            }
    }

    // ---------- stage 2: Act @ W2[n] -> relu -> Act ----------
    gemm_stage(acc, W2 + (size_t)n*H_*H_, Act, Bs, tid, tx, ty, H_);
    {
        const float* bp = b2 + n*H_;
        float4 u = *(const float4*)(bp + tx*8);
        float4 v = *(const float4*)(bp + tx*8 + 4);
        float bb[8] = {u.x,u.y,u.z,u.w,v.x,v.y,v.z,v.w};
        __syncthreads();
        #pragma unroll
        for (int i = 0; i < 8; i++)
            #pragma unroll
            for (int j = 0; j < 8; j++) {
                Act[(ty*8+i)*ACT_STRIDE + tx*8 + j] = fmaxf(acc[i][j] + bb[j], 0.f);
                acc[i][j] = 0.f;
            }
    }

    // ---------- stage 3: Act @ W3[n] + b3 -> q (raw) -> Act ----------
    gemm_stage(acc, W3 + (size_t)n*H_*E_, Act, Bs, tid, tx, ty, H_);
    {
        const float* bp = b3 + n*E_;
        float4 u = *(const float4*)(bp + tx*8);
        float4 v = *(const float4*)(bp + tx*8 + 4);
        float bb[8] = {u.x,u.y,u.z,u.w,v.x,v.y,v.z,v.w};
        __syncthreads();
        #pragma unroll
        for (int i = 0; i < 8; i++)
            #pragma unroll
            for (int j = 0; j < 8; j++)
                Act[(ty*8+i)*ACT_STRIDE + tx*8 + j] = acc[i][j] + bb[j];
    }
    __syncthreads();

    // ---------- per-row epilogue ----------
    if (tid < 128) {
        int r = tid;
        const float* qr = Act + r*ACT_STRIDE;
        int t = task_id[b0 + r];
        const float* lr = lang + (size_t)t * E_;
        float nq = 0.f, dot = 0.f, nl = 0.f;
        #pragma unroll 8
        for (int e = 0; e < E_; e++) {
            float q = qr[e];
            float L = lr[e];
            nq  = fmaf(q, q, nq);
            dot = fmaf(q, L, dot);
            nl  = fmaf(L, L, nl);
        }
        float iq = rsqrtf(nq);
        float il = 1.f / fmaxf(sqrtf(nl), 1e-8f);
        g_cos[(size_t)(b0+r)*N_ + n] = dot * iq * il;

        const float* pr = prior + (size_t)(b0+r)*N_;
        float m = -INFINITY;
        for (int nn = 0; nn < N_; nn++) m = fmaxf(m, pr[nn]);
        float s = 0.f, me = 0.f;
        for (int nn = 0; nn < N_; nn++) {
            float e_ = expf(pr[nn] - m);
            s += e_;
            if (nn == n) me = e_;
        }
        pw[r]   = (me / s) * iq;
        invq[r] = iq;
        trow[r] = (t == n);
    }
    __syncthreads();

    // scatter: latent accumulation + latent_target
    for (int idx = tid; idx < 128*128; idx += 256) {
        int r = idx >> 7, e = idx & 127;
        float q = Act[r*ACT_STRIDE + e];
        atomicAdd(&g_lat[(size_t)(b0+r)*E_ + e], pw[r] * q);
        if (trow[r]) out_lt[(size_t)(b0+r)*E_ + e] = q * invq[r];
    }
}

__global__ void enc_finalize(const float* __restrict__ state, float* __restrict__ out)
{
    int warp = (blockIdx.x * blockDim.x + threadIdx.x) >> 5;
    int lane = threadIdx.x & 31;
    if (warp >= B_) return;
    size_t b = warp;

    // log_softmax(cos/TEMP)
    float x0 = (lane      < N_) ? g_cos[b*N_ + lane]      * 10.0f : -INFINITY;
    float x1 = (lane + 32 < N_) ? g_cos[b*N_ + lane + 32] * 10.0f : -INFINITY;
    float m = fmaxf(x0, x1);
    #pragma unroll
    for (int off = 16; off > 0; off >>= 1)
        m = fmaxf(m, __shfl_xor_sync(0xffffffffu, m, off));
    float s = expf(x0 - m) + expf(x1 - m);
    #pragma unroll
    for (int off = 16; off > 0; off >>= 1)
        s += __shfl_xor_sync(0xffffffffu, s, off);
    float lse = m + logf(s);
    float* lp = out + LP_OFF + b*N_;
    if (lane      < N_) lp[lane]      = x0 - lse;
    if (lane + 32 < N_) lp[lane + 32] = x1 - lse;

    // rep_vec = [state, latent_vec]; latent_vec output
    float* rep = out + REP_OFF + b*(S_+E_);
    const float* st = state + b*S_;
    for (int j = lane; j < S_/4; j += 32)
        ((float4*)rep)[j] = ((const float4*)st)[j];
    float* lv = out + LV_OFF + b*E_;
    const float* la = g_lat + b*E_;
    for (int j = lane; j < E_/4; j += 32) {
        float4 v = ((const float4*)la)[j];
        ((float4*)(rep + S_))[j] = v;
        ((float4*)lv)[j] = v;
    }
}

extern "C" void kernel_launch(void* const* d_in, const int* in_sizes, int n_in,
                              void* d_out, int out_size)
{
    const float* state  = (const float*)d_in[0];
    const int*   tid    = (const int*)  d_in[1];
    const float* prior  = (const float*)d_in[2];
    const float* W1     = (const float*)d_in[3];
    const float* b1     = (const float*)d_in[4];
    const float* W2     = (const float*)d_in[5];
    const float* b2     = (const float*)d_in[6];
    const float* W3     = (const float*)d_in[7];
    const float* b3     = (const float*)d_in[8];
    const float* lang   = (const float*)d_in[9];
    float* out = (float*)d_out;

    cudaFuncSetAttribute(enc_main, cudaFuncAttributeMaxDynamicSharedMemorySize, (int)SMEM_BYTES);

    zero_lat_kernel<<<2048, 256>>>();
    enc_main<<<dim3(N_, B_/128), 256, SMEM_BYTES>>>(
        state, tid, prior, W1, b1, W2, b2, W3, b3, lang, out + LT_OFF);
    enc_finalize<<<2048, 256>>>(state, out);
}

// round 5
// speedup vs baseline: 2.2796x; 2.2796x over previous
#include <cuda_runtime.h>
#include <cuda_bf16.h>
#include <math.h>
#include <stdint.h>

#define B_  16384
#define S_  256
#define E_  128
#define H_  128
#define NT  34

// output layout (floats): rep_vec [B,384] | log_task_prob [B,34] | latent_target [B,128] | latent_vec [B,128]
#define LP_OFF   ((size_t)B_*(S_+E_))
#define LT_OFF   (LP_OFF + (size_t)B_*NT)
#define LV_OFF   (LT_OFF + (size_t)B_*E_)

// ---------------- preconverted bf16 hi/lo + normalized-lang globals ----------------
__device__ __align__(256) __nv_bfloat16 g_s_hi[(size_t)B_*S_];
__device__ __align__(256) __nv_bfloat16 g_s_lo[(size_t)B_*S_];
__device__ __align__(256) __nv_bfloat16 g_w1_hi[(size_t)NT*H_*S_];   // [n][j][k] transposed
__device__ __align__(256) __nv_bfloat16 g_w1_lo[(size_t)NT*H_*S_];
__device__ __align__(256) __nv_bfloat16 g_w2_hi[(size_t)NT*H_*H_];
__device__ __align__(256) __nv_bfloat16 g_w2_lo[(size_t)NT*H_*H_];
__device__ __align__(256) __nv_bfloat16 g_w3_hi[(size_t)NT*E_*H_];
__device__ __align__(256) __nv_bfloat16 g_w3_lo[(size_t)NT*E_*H_];
__device__ __align__(256) float         g_lns [(size_t)B_*E_];       // lang[task_id[b]] normalized

#define NSZ  ((size_t)B_*S_)
#define N1SZ ((size_t)NT*H_*S_)
#define N2SZ ((size_t)NT*H_*H_)
#define N3SZ ((size_t)NT*E_*H_)
#define PRETOT (NSZ+N1SZ+N2SZ+N3SZ)

__global__ void preconv(const float* __restrict__ state, const float* __restrict__ W1,
                        const float* __restrict__ W2, const float* __restrict__ W3)
{
    size_t idx = (size_t)blockIdx.x*256 + threadIdx.x;
    if (idx >= PRETOT) return;
    float v; __nv_bfloat16* ph; __nv_bfloat16* pl; size_t o;
    if (idx < NSZ) {
        v = state[idx]; ph = g_s_hi; pl = g_s_lo; o = idx;
    } else if (idx < NSZ+N1SZ) {
        size_t r = idx - NSZ;
        int n = (int)(r / (H_*S_)); int rem = (int)(r % (H_*S_));
        int j = rem / S_, k = rem % S_;
        v = W1[(size_t)n*S_*H_ + (size_t)k*H_ + j];
        ph = g_w1_hi; pl = g_w1_lo; o = r;
    } else if (idx < NSZ+N1SZ+N2SZ) {
        size_t r = idx - NSZ - N1SZ;
        int n = (int)(r / (H_*H_)); int rem = (int)(r % (H_*H_));
        int j = rem / H_, k = rem % H_;
        v = W2[(size_t)n*H_*H_ + (size_t)k*H_ + j];
        ph = g_w2_hi; pl = g_w2_lo; o = r;
    } else {
        size_t r = idx - NSZ - N1SZ - N2SZ;
        int n = (int)(r / (E_*H_)); int rem = (int)(r % (E_*H_));
        int j = rem / H_, k = rem % H_;
        v = W3[(size_t)n*H_*E_ + (size_t)k*E_ + j];
        ph = g_w3_hi; pl = g_w3_lo; o = r;
    }
    __nv_bfloat16 h = __float2bfloat16_rn(v);
    float lo = v - __bfloat162float(h);
    ph[o] = h;
    pl[o] = __float2bfloat16_rn(lo);
}

__global__ void lns_kernel(const float* __restrict__ lang, const int* __restrict__ task_id)
{
    int w = (blockIdx.x*blockDim.x + threadIdx.x) >> 5;
    int lane = threadIdx.x & 31;
    if (w >= B_) return;
    int t = task_id[w];
    const float4 u = *(const float4*)(lang + (size_t)t*E_ + lane*4);
    float s = u.x*u.x + u.y*u.y + u.z*u.z + u.w*u.w;
    #pragma unroll
    for (int off = 16; off > 0; off >>= 1) s += __shfl_xor_sync(0xffffffffu, s, off);
    float il = 1.f / fmaxf(sqrtf(s), 1e-8f);
    float4 o = make_float4(u.x*il, u.y*il, u.z*il, u.w*il);
    *(float4*)(g_lns + (size_t)w*E_ + lane*4) = o;
}

// ---------------- asm helpers ----------------
__device__ __forceinline__ uint32_t smem_u32(const void* p) {
    uint32_t a;
    asm("{ .reg .u64 t; cvta.to.shared.u64 t, %1; cvt.u32.u64 %0, t; }" : "=r"(a) : "l"(p));
    return a;
}
__device__ __forceinline__ void cpa_cg(uint32_t dst, const void* src) {
    asm volatile("cp.async.cg.shared.global [%0], [%1], 16;" :: "r"(dst), "l"(src) : "memory");
}
#define CP_COMMIT() asm volatile("cp.async.commit_group;" ::: "memory")
#define CP_WAIT1()  asm volatile("cp.async.wait_group 1;" ::: "memory")

#define LDSM4(r, addr) \
    asm volatile("ldmatrix.sync.aligned.m8n8.x4.shared.b16 {%0,%1,%2,%3}, [%4];" \
        : "=r"((r)[0]), "=r"((r)[1]), "=r"((r)[2]), "=r"((r)[3]) : "r"(addr))

#define MMA16816(c, a, b) \
    asm volatile("mma.sync.aligned.m16n8k16.row.col.f32.bf16.bf16.f32 " \
        "{%0,%1,%2,%3}, {%4,%5,%6,%7}, {%8,%9}, {%0,%1,%2,%3};" \
        : "+f"((c)[0]), "+f"((c)[1]), "+f"((c)[2]), "+f"((c)[3]) \
        : "r"((a)[0]), "r"((a)[1]), "r"((a)[2]), "r"((a)[3]), "r"((b)[0]), "r"((b)[1]))

// ---------------- SMEM map (bytes from dynamic base) ----------------
#define CH    0        // 2 bufs x 4 mats(A_hi,A_lo,B_hi,B_lo) x 16384 = 131072
#define ACT   131072   // act_hi [2 panels x 16384] ; act_lo at +32768
#define RED   196608   // [4 warps][128 rows][2] floats = 4096
#define PWB   200704   // 128 floats
#define IQB   201216
#define TGB   201728   // 128 ints
#define BIA   202240   // 3 x 128 floats
#define SMEM_TOTAL 203776

__device__ __forceinline__ void issue_loads(int n, int s, int c, uint32_t dstbase,
                                            int tid, int b0)
{
    if (n >= NT) return;
    const int kw0 = c * 64;
    const int Kfull = (s == 0) ? S_ : H_;
    const __nv_bfloat16 *wh, *wl;
    if (s == 0)      { wh = g_w1_hi + (size_t)n*H_*S_; wl = g_w1_lo + (size_t)n*H_*S_; }
    else if (s == 1) { wh = g_w2_hi + (size_t)n*H_*H_; wl = g_w2_lo + (size_t)n*H_*H_; }
    else             { wh = g_w3_hi + (size_t)n*E_*H_; wl = g_w3_lo + (size_t)n*E_*H_; }
    #pragma unroll
    for (int i = 0; i < 4; i++) {
        int u = tid + i*256;
        int j = u >> 3, kb = u & 7;
        uint32_t sw = (uint32_t)(u*16);
        sw = sw ^ ((sw >> 3) & 0x70);
        size_t so = (size_t)j*Kfull + kw0 + kb*8;
        cpa_cg(dstbase + 32768 + sw, wh + so);
        cpa_cg(dstbase + 49152 + sw, wl + so);
        if (s == 0) {
            size_t ao = (size_t)(b0 + j)*S_ + kw0 + kb*8;
            cpa_cg(dstbase +     0 + sw, g_s_hi + ao);
            cpa_cg(dstbase + 16384 + sw, g_s_lo + ao);
        }
    }
}

__device__ __forceinline__ void mma_chunk(uint32_t aH, uint32_t aL, uint32_t bH, uint32_t bL,
                                          float acc[4][4][4], int lane, int RB, int CB)
{
    const uint32_t xorv = (uint32_t)((lane & 7) << 4);
    const uint32_t tA = (uint32_t)((lane >> 4) * 16);        // A k-half from lane
    const uint32_t tB = (uint32_t)(((lane >> 3) & 1) * 16);  // B k-half from lane
    uint32_t baseA[4], baseB[2];
    #pragma unroll
    for (int mt = 0; mt < 4; mt++)
        baseA[mt] = (uint32_t)((RB + mt*16 + (lane & 15)) * 128);
    #pragma unroll
    for (int np = 0; np < 2; np++)
        baseB[np] = (uint32_t)((CB + np*16 + ((lane >> 4) * 8) + (lane & 7)) * 128);

    #pragma unroll
    for (int kk = 0; kk < 4; kk++) {
        const uint32_t offA = ((uint32_t)(kk*32) + tA) ^ xorv;
        const uint32_t offB = ((uint32_t)(kk*32) + tB) ^ xorv;
        uint32_t ah[4][4], al[4][4], bh[2][4], bl[2][4];
        #pragma unroll
        for (int mt = 0; mt < 4; mt++) {
            LDSM4(ah[mt], aH + baseA[mt] + offA);
            LDSM4(al[mt], aL + baseA[mt] + offA);
        }
        #pragma unroll
        for (int np = 0; np < 2; np++) {
            LDSM4(bh[np], bH + baseB[np] + offB);
            LDSM4(bl[np], bL + baseB[np] + offB);
        }
        #pragma unroll
        for (int mt = 0; mt < 4; mt++)
            #pragma unroll
            for (int np = 0; np < 2; np++)
                #pragma unroll
                for (int h = 0; h < 2; h++) {
                    const int nt = np*2 + h;
                    MMA16816(acc[mt][nt], ah[mt], (&bh[np][h*2]));
                    MMA16816(acc[mt][nt], ah[mt], (&bl[np][h*2]));
                    MMA16816(acc[mt][nt], al[mt], (&bh[np][h*2]));
                }
    }
}

__global__ __launch_bounds__(256, 1) void enc_main(
    const float* __restrict__ state, const int* __restrict__ task_id,
    const float* __restrict__ prior,
    const float* __restrict__ b1, const float* __restrict__ b2,
    const float* __restrict__ b3, float* __restrict__ out)
{
    extern __shared__ __align__(1024) char sm[];
    const int tid  = threadIdx.x;
    const int lane = tid & 31;
    const int wid  = tid >> 5;
    const int wm   = wid >> 2;        // 0..1
    const int wn   = wid & 3;         // 0..3
    const int RB   = wm * 64;
    const int CB   = wn * 32;
    const int b0   = blockIdx.x * 128;
    const uint32_t smb = smem_u32(sm);

    float* red  = (float*)(sm + RED);
    float* pwb  = (float*)(sm + PWB);
    float* iqb  = (float*)(sm + IQB);
    int*   tgb  = (int*)  (sm + TGB);
    float* bia  = (float*)(sm + BIA);

    float acc[4][4][4];
    float lat[4][4][4];
    #pragma unroll
    for (int a = 0; a < 4; a++)
        #pragma unroll
        for (int b = 0; b < 4; b++)
            #pragma unroll
            for (int c = 0; c < 4; c++) { acc[a][b][c] = 0.f; lat[a][b][c] = 0.f; }

    // per-row (thread < 128) state
    int   trow = 0;
    float pm = 0.f, psinv = 0.f;
    float msoft = -INFINITY, ssoft = 0.f;
    if (tid < 128) {
        trow = task_id[b0 + tid];
        const float* pr = prior + (size_t)(b0 + tid) * NT;
        float m = -INFINITY;
        for (int nn = 0; nn < NT; nn++) m = fmaxf(m, pr[nn]);
        float s = 0.f;
        for (int nn = 0; nn < NT; nn++) s += expf(pr[nn] - m);
        pm = m; psinv = 1.f / s;
    }

    // prologue: prefetch chunk (n=0,s=0,c=0) into buf 0
    issue_loads(0, 0, 0, smb + CH, tid, b0);
    CP_COMMIT();
    int g = 0;

    for (int n = 0; n < NT; n++) {
        __syncthreads();   // protect BIA rewrite vs previous task's epilogue reads
        if (tid < 128) {
            bia[tid]       = b1[n*H_ + tid];
            bia[128 + tid] = b2[n*H_ + tid];
            bia[256 + tid] = b3[n*E_ + tid];
        }
        for (int s = 0; s < 3; s++) {
            const int nc = (s == 0) ? 4 : 2;
            for (int c = 0; c < nc; c++) {
                // prefetch next chunk (possibly next stage / next task)
                int cc2 = c + 1, ss2 = s, nn2 = n;
                if (cc2 == nc) { cc2 = 0; ss2 = s + 1; if (ss2 == 3) { ss2 = 0; nn2 = n + 1; } }
                issue_loads(nn2, ss2, cc2, smb + CH + (uint32_t)(((g+1)&1)*65536), tid, b0);
                CP_COMMIT();
                CP_WAIT1();
                __syncthreads();
                const uint32_t bufb = smb + CH + (uint32_t)((g&1)*65536);
                uint32_t aH, aL;
                if (s == 0) { aH = bufb; aL = bufb + 16384; }
                else        { aH = smb + ACT + (uint32_t)(c*16384); aL = aH + 32768; }
                mma_chunk(aH, aL, bufb + 32768, bufb + 49152, acc, lane, RB, CB);
                __syncthreads();
                g++;
            }

            if (s < 2) {
                // epilogue: relu(acc + bias) -> bf16 hi/lo -> act panels
                const float* bs = bia + s*128;
                #pragma unroll
                for (int mt = 0; mt < 4; mt++) {
                    const int rA = RB + mt*16 + (lane >> 2);
                    const int rB2 = rA + 8;
                    #pragma unroll
                    for (int nt = 0; nt < 4; nt++) {
                        const int col = CB + nt*8 + (lane & 3)*2;
                        float v0 = fmaxf(acc[mt][nt][0] + bs[col],   0.f);
                        float v1 = fmaxf(acc[mt][nt][1] + bs[col+1], 0.f);
                        float v2 = fmaxf(acc[mt][nt][2] + bs[col],   0.f);
                        float v3 = fmaxf(acc[mt][nt][3] + bs[col+1], 0.f);
                        acc[mt][nt][0] = 0.f; acc[mt][nt][1] = 0.f;
                        acc[mt][nt][2] = 0.f; acc[mt][nt][3] = 0.f;
                        __nv_bfloat16 h0 = __float2bfloat16_rn(v0), h1 = __float2bfloat16_rn(v1);
                        __nv_bfloat16 h2 = __float2bfloat16_rn(v2), h3 = __float2bfloat16_rn(v3);
                        __nv_bfloat16 l0 = __float2bfloat16_rn(v0 - __bfloat162float(h0));
                        __nv_bfloat16 l1 = __float2bfloat16_rn(v1 - __bfloat162float(h1));
                        __nv_bfloat16 l2 = __float2bfloat16_rn(v2 - __bfloat162float(h2));
                        __nv_bfloat16 l3 = __float2bfloat16_rn(v3 - __bfloat162float(h3));
                        const int p = col >> 6;
                        uint32_t oA = (uint32_t)(rA *128 + (col & 63)*2); oA ^= ((oA >> 3) & 0x70);
                        uint32_t oB = (uint32_t)(rB2*128 + (col & 63)*2); oB ^= ((oB >> 3) & 0x70);
                        char* basep = sm + ACT + p*16384;
                        *(uint32_t*)(basep + oA) =
                            (uint32_t)__bfloat16_as_ushort(h0) | ((uint32_t)__bfloat16_as_ushort(h1) << 16);
                        *(uint32_t*)(basep + oB) =
                            (uint32_t)__bfloat16_as_ushort(h2) | ((uint32_t)__bfloat16_as_ushort(h3) << 16);
                        *(uint32_t*)(basep + 32768 + oA) =
                            (uint32_t)__bfloat16_as_ushort(l0) | ((uint32_t)__bfloat16_as_ushort(l1) << 16);
                        *(uint32_t*)(basep + 32768 + oB) =
                            (uint32_t)__bfloat16_as_ushort(l2) | ((uint32_t)__bfloat16_as_ushort(l3) << 16);
                    }
                }
                // act visible to next stage's first mma via that stage's first barrier
            } else {
                // ---- stage-2 epilogue ----
                const float* b3s = bia + 256;
                // pass 1: row partials for ||q||^2 and q . lang_norm
                #pragma unroll
                for (int mt = 0; mt < 4; mt++) {
                    const int rA = RB + mt*16 + (lane >> 2);
                    const int rB2 = rA + 8;
                    float nqA = 0.f, dA = 0.f, nqB = 0.f, dB = 0.f;
                    #pragma unroll
                    for (int nt = 0; nt < 4; nt++) {
                        const int col = CB + nt*8 + (lane & 3)*2;
                        const float bb0 = b3s[col], bb1 = b3s[col+1];
                        float q0 = acc[mt][nt][0] + bb0;
                        float q1 = acc[mt][nt][1] + bb1;
                        float q2 = acc[mt][nt][2] + bb0;
                        float q3 = acc[mt][nt][3] + bb1;
                        const float2 LA = *(const float2*)(g_lns + (size_t)(b0+rA)*E_ + col);
                        const float2 LB = *(const float2*)(g_lns + (size_t)(b0+rB2)*E_ + col);
                        nqA = fmaf(q0,q0, fmaf(q1,q1, nqA));
                        nqB = fmaf(q2,q2, fmaf(q3,q3, nqB));
                        dA  = fmaf(q0,LA.x, fmaf(q1,LA.y, dA));
                        dB  = fmaf(q2,LB.x, fmaf(q3,LB.y, dB));
                    }
                    #pragma unroll
                    for (int off = 1; off <= 2; off <<= 1) {
                        nqA += __shfl_xor_sync(0xffffffffu, nqA, off);
                        dA  += __shfl_xor_sync(0xffffffffu, dA,  off);
                        nqB += __shfl_xor_sync(0xffffffffu, nqB, off);
                        dB  += __shfl_xor_sync(0xffffffffu, dB,  off);
                    }
                    if ((lane & 3) == 0) {
                        *(float2*)(red + ((size_t)wn*128 + rA )*2) = make_float2(nqA, dA);
                        *(float2*)(red + ((size_t)wn*128 + rB2)*2) = make_float2(nqB, dB);
                    }
                }
                __syncthreads();
                if (tid < 128) {
                    const int r = tid;
                    float nq = 0.f, dot = 0.f;
                    #pragma unroll
                    for (int w = 0; w < 4; w++) {
                        float2 v = *(const float2*)(red + ((size_t)w*128 + r)*2);
                        nq += v.x; dot += v.y;
                    }
                    float iq = rsqrtf(nq);
                    float x = dot * iq * 10.0f;
                    float prn = prior[(size_t)(b0 + r)*NT + n];
                    float pw = expf(prn - pm) * psinv * iq;
                    float mn = fmaxf(msoft, x);
                    ssoft = ssoft * expf(msoft - mn) + expf(x - mn);
                    msoft = mn;
                    out[LP_OFF + (size_t)(b0 + r)*NT + n] = x;
                    pwb[r] = pw; iqb[r] = iq; tgb[r] = (trow == n) ? 1 : 0;
                }
                __syncthreads();
                // pass 2: latent accumulate + target scatter
                #pragma unroll
                for (int mt = 0; mt < 4; mt++) {
                    const int rA = RB + mt*16 + (lane >> 2);
                    const int rB2 = rA + 8;
                    const float pwA = pwb[rA], pwB = pwb[rB2];
                    const float iqA = iqb[rA], iqB = iqb[rB2];
                    const int tgA = tgb[rA], tgB = tgb[rB2];
                    #pragma unroll
                    for (int nt = 0; nt < 4; nt++) {
                        const int col = CB + nt*8 + (lane & 3)*2;
                        const float bb0 = b3s[col], bb1 = b3s[col+1];
                        float q0 = acc[mt][nt][0] + bb0;
                        float q1 = acc[mt][nt][1] + bb1;
                        float q2 = acc[mt][nt][2] + bb0;
                        float q3 = acc[mt][nt][3] + bb1;
                        lat[mt][nt][0] = fmaf(pwA, q0, lat[mt][nt][0]);
                        lat[mt][nt][1] = fmaf(pwA, q1, lat[mt][nt][1]);
                        lat[mt][nt][2] = fmaf(pwB, q2, lat[mt][nt][2]);
                        lat[mt][nt][3] = fmaf(pwB, q3, lat[mt][nt][3]);
                        if (tgA) *(float2*)(out + LT_OFF + (size_t)(b0+rA)*E_ + col)
                                    = make_float2(q0*iqA, q1*iqA);
                        if (tgB) *(float2*)(out + LT_OFF + (size_t)(b0+rB2)*E_ + col)
                                    = make_float2(q2*iqB, q3*iqB);
                        acc[mt][nt][0] = 0.f; acc[mt][nt][1] = 0.f;
                        acc[mt][nt][2] = 0.f; acc[mt][nt][3] = 0.f;
                    }
                }
            }
        }
    }

    // ---------------- final outputs ----------------
    if (tid < 128) {
        float lse = msoft + logf(ssoft);
        float* lp = out + LP_OFF + (size_t)(b0 + tid)*NT;
        #pragma unroll
        for (int nn = 0; nn < NT; nn++) lp[nn] -= lse;
    }
    // rep_vec state part
    for (int i = tid; i < 128*64; i += 256) {
        const int r = i >> 6, j = i & 63;
        float4 v = *(const float4*)(state + (size_t)(b0+r)*S_ + j*4);
        *(float4*)(out + (size_t)(b0+r)*(S_+E_) + j*4) = v;
    }
    // latent: rep_vec tail + latent_vec output, straight from register fragments
    #pragma unroll
    for (int mt = 0; mt < 4; mt++) {
        const int rA = RB + mt*16 + (lane >> 2);
        const int rB2 = rA + 8;
        #pragma unroll
        for (int nt = 0; nt < 4; nt++) {
            const int col = CB + nt*8 + (lane & 3)*2;
            float2 vA = make_float2(lat[mt][nt][0], lat[mt][nt][1]);
            float2 vB = make_float2(lat[mt][nt][2], lat[mt][nt][3]);
            *(float2*)(out + (size_t)(b0+rA )*(S_+E_) + S_ + col) = vA;
            *(float2*)(out + (size_t)(b0+rB2)*(S_+E_) + S_ + col) = vB;
            *(float2*)(out + LV_OFF + (size_t)(b0+rA )*E_ + col) = vA;
            *(float2*)(out + LV_OFF + (size_t)(b0+rB2)*E_ + col) = vB;
        }
    }
}

extern "C" void kernel_launch(void* const* d_in, const int* in_sizes, int n_in,
                              void* d_out, int out_size)
{
    (void)in_sizes; (void)n_in; (void)out_size;
    const float* state  = (const float*)d_in[0];
    const int*   tsk    = (const int*)  d_in[1];
    const float* prior  = (const float*)d_in[2];
    const float* W1     = (const float*)d_in[3];
    const float* b1     = (const float*)d_in[4];
    const float* W2     = (const float*)d_in[5];
    const float* b2     = (const float*)d_in[6];
    const float* W3     = (const float*)d_in[7];
    const float* b3     = (const float*)d_in[8];
    const float* lang   = (const float*)d_in[9];
    float* out = (float*)d_out;

    cudaFuncSetAttribute(enc_main, cudaFuncAttributeMaxDynamicSharedMemorySize, SMEM_TOTAL);

    preconv<<<(unsigned)((PRETOT + 255)/256), 256>>>(state, W1, W2, W3);
    lns_kernel<<<B_*32/256, 256>>>(lang, tsk);
    enc_main<<<B_/128, 256, SMEM_TOTAL>>>(state, tsk, prior, b1, b2, b3, out);
}